// round 6
// baseline (speedup 1.0000x reference)
#include <cuda_runtime.h>
#include <stdint.h>

// RGBMem: inverted-index single-sweep, fully fused (2 launches).
//   logits[b,k] = dot(memory[row(b,k)], x[b]) / T,  row(b,0)=y[b], else idx[b,k]
//   labels = zeros
//   new_memory = memory with rows y[b] := normalize(0.5*memory[y]+0.5*x[b])
// Output (float32): [logits (bsz*Kp1)] [labels gap] [memory (n_data*128)]
// build: row->slot inverted lists + update flags. sweep: one streaming table
// pass does copy, all dots, and the EMA rows. Counters/flags self-clean so
// graph replays start from a zeroed state without a zero kernel.

#define T_INV (1.0f / 0.07f)
#define MAX_ROWS 524288
#define CAP 16

__device__ unsigned g_count[MAX_ROWS];               // zero-init, self-cleaned
__device__ unsigned g_upd[MAX_ROWS];                 // zero-init, self-cleaned
__device__ unsigned g_list[(size_t)MAX_ROWS * CAP];  // 32 MB scratch

__device__ __forceinline__ long long load_index(const void* p, unsigned i,
                                                int is64) {
    if (is64) return ((const long long*)p)[i];
    return (long long)((const int*)p)[i];
}

__device__ __forceinline__ int sniff_is64(const void* idx) {
    const unsigned* w = (const unsigned*)idx;
    int is64 = 1;
    #pragma unroll
    for (int i = 0; i < 16; i++)
        if (w[2 * i + 1] != 0u) { is64 = 0; break; }
    return is64;
}

// ---------------------------------------------------------------------------
// Build: inverted lists, update flags, labels zeroing.
// ---------------------------------------------------------------------------
__global__ void build_kernel(const float* __restrict__ x,
                             const void* __restrict__ y,
                             const void* __restrict__ idx,
                             const float* __restrict__ memory,
                             float* __restrict__ logits,
                             float* __restrict__ out_labels, int label_elems,
                             int bsz, unsigned Kp1, long long n_data) {
    __shared__ int s_is64;
    if (threadIdx.x == 0) s_is64 = sniff_is64(idx);
    __syncthreads();
    int is64 = s_is64;

    if (blockIdx.x == 0) {
        // update flags: max-b wins == "last write wins" for duplicate y
        if (threadIdx.x < (unsigned)bsz) {
            long long r = load_index(y, threadIdx.x, is64);
            r = r < 0 ? 0 : (r >= n_data ? n_data - 1 : r);
            atomicMax(&g_upd[r], threadIdx.x + 1u);
        }
        for (int t = threadIdx.x; t < label_elems; t += blockDim.x)
            out_labels[t] = 0.0f;
    }

    unsigned total = (unsigned)bsz * Kp1;
    unsigned i = blockIdx.x * blockDim.x + threadIdx.x;
    unsigned stride = gridDim.x * blockDim.x;
    for (; i < total; i += stride) {
        unsigned b = i / Kp1;
        unsigned k = i - b * Kp1;
        long long row = (k == 0) ? load_index(y, b, is64)
                                 : load_index(idx, i, is64);
        row = row < 0 ? 0 : (row >= n_data ? n_data - 1 : row);
        unsigned p = atomicAdd(&g_count[row], 1u);
        if (p < CAP) {
            g_list[(size_t)row * CAP + p] = i;
        } else {
            // direct fallback (Poisson tail, ~never; keeps CAP safe)
            const float* mr = memory + row * 128;
            const float* xr = x + b * 128;
            float s = 0.0f;
            for (int d = 0; d < 128; d++) s += __ldg(mr + d) * __ldg(xr + d);
            logits[i] = s * T_INV;
        }
    }
}

// ---------------------------------------------------------------------------
// Sweep: one warp per 4 consecutive rows (MLP=4). Copy or EMA-update each
// row, compute its logits while resident in registers. Self-clean counters.
// ---------------------------------------------------------------------------
__global__ void __launch_bounds__(256) sweep_kernel(
    const float* __restrict__ x,
    const float4* __restrict__ mem4,
    float4* __restrict__ out_mem4,
    float* __restrict__ logits,
    int bsz, unsigned Kp1, long long n_data) {
    __shared__ float4 xs[16 * 32];
    int tid = threadIdx.x;
    int nx4 = bsz * 32;
    for (int i = tid; i < nx4; i += blockDim.x) xs[i] = ((const float4*)x)[i];
    __syncthreads();

    int lane = tid & 31;
    long long warp = ((long long)blockIdx.x * blockDim.x + tid) >> 5;
    long long nwarps = ((long long)gridDim.x * blockDim.x) >> 5;

    for (long long r0 = warp * 4; r0 < n_data; r0 += nwarps * 4) {
        float4 m[4];
        unsigned cnt[4], upd[4];
        // issue all independent loads first (MLP)
        #pragma unroll
        for (int j = 0; j < 4; j++) {
            long long r = r0 + j;
            if (r < n_data) {
                m[j] = __ldcs(mem4 + r * 32 + lane);
                cnt[j] = g_count[r];
                upd[j] = g_upd[r];
            } else { cnt[j] = 0; upd[j] = 0; }
        }
        #pragma unroll
        for (int j = 0; j < 4; j++) {
            long long r = r0 + j;
            if (r >= n_data) continue;

            // ---- logits from ORIGINAL row data ----
            unsigned c = cnt[j] > CAP ? CAP : cnt[j];
            const unsigned* lst = g_list + (size_t)r * CAP;
            for (unsigned e = 0; e < c; e++) {
                unsigned i = lst[e];                 // broadcast load
                unsigned b = i / Kp1;
                float4 xv = xs[b * 32 + lane];
                float s = m[j].x * xv.x + m[j].y * xv.y +
                          m[j].z * xv.z + m[j].w * xv.w;
                #pragma unroll
                for (int off = 16; off; off >>= 1)
                    s += __shfl_xor_sync(0xffffffffu, s, off);
                if (lane == 0) logits[i] = s * T_INV;
            }

            // ---- copy out, or EMA+normalize if flagged ----
            if (upd[j] == 0) {
                __stcs(out_mem4 + r * 32 + lane, m[j]);
            } else {
                unsigned b = upd[j] - 1u;
                float4 xv = xs[b * 32 + lane];
                float4 v;
                v.x = 0.5f * m[j].x + 0.5f * xv.x;
                v.y = 0.5f * m[j].y + 0.5f * xv.y;
                v.z = 0.5f * m[j].z + 0.5f * xv.z;
                v.w = 0.5f * m[j].w + 0.5f * xv.w;
                float s = v.x * v.x + v.y * v.y + v.z * v.z + v.w * v.w;
                #pragma unroll
                for (int off = 16; off; off >>= 1)
                    s += __shfl_xor_sync(0xffffffffu, s, off);
                float inv = 1.0f / fmaxf(sqrtf(s), 1e-12f);
                v.x *= inv; v.y *= inv; v.z *= inv; v.w *= inv;
                __stcs(out_mem4 + r * 32 + lane, v);
            }

            // ---- self-clean for next graph replay ----
            if (lane == 0) { g_count[r] = 0u; g_upd[r] = 0u; }
        }
    }
}

// ---------------------------------------------------------------------------
// Fallback path (n_data > MAX_ROWS): R2-proven kernels.
// ---------------------------------------------------------------------------
__global__ void copy_mem_kernel(const float4* __restrict__ src,
                                float4* __restrict__ dst, long long n4) {
    long long i = (long long)blockIdx.x * blockDim.x + threadIdx.x;
    long long stride = (long long)gridDim.x * blockDim.x;
    for (; i < n4; i += stride) dst[i] = src[i];
}

__global__ void logits_kernel(const float* __restrict__ x,
                              const void* __restrict__ y,
                              const void* __restrict__ idx,
                              const float* __restrict__ memory,
                              float* __restrict__ logits,
                              int bsz, unsigned Kp1, long long n_data) {
    __shared__ float4 xs[16 * 32];
    __shared__ int s_is64;
    int tid = threadIdx.x;
    if (tid == 0) s_is64 = sniff_is64(idx);
    int nx4 = bsz * 32;
    for (int i = tid; i < nx4; i += blockDim.x) xs[i] = ((const float4*)x)[i];
    __syncthreads();
    int is64 = s_is64;

    int lane = tid & 31;
    unsigned warp = (blockIdx.x * blockDim.x + tid) >> 5;
    unsigned nwarps = (gridDim.x * blockDim.x) >> 5;
    unsigned total = (unsigned)bsz * Kp1;

    for (unsigned i = warp; i < total; i += nwarps) {
        unsigned b = i / Kp1;
        unsigned k = i - b * Kp1;
        long long row = (k == 0) ? load_index(y, b, is64)
                                 : load_index(idx, i, is64);
        row = row < 0 ? 0 : (row >= n_data ? n_data - 1 : row);
        float4 mm = __ldg((const float4*)(memory + row * 128) + lane);
        float4 xv = xs[b * 32 + lane];
        float s = mm.x * xv.x + mm.y * xv.y + mm.z * xv.z + mm.w * xv.w;
        #pragma unroll
        for (int off = 16; off; off >>= 1)
            s += __shfl_xor_sync(0xffffffffu, s, off);
        if (lane == 0) logits[i] = s * T_INV;
    }
}

__global__ void update_kernel(const float* __restrict__ x,
                              const void* __restrict__ y,
                              const void* __restrict__ idx,
                              const float* __restrict__ memory,
                              float* __restrict__ out_mem,
                              float* __restrict__ out_labels,
                              int label_elems, long long n_data) {
    int b = blockIdx.x;
    int t = threadIdx.x;
    __shared__ int s_is64;
    if (t == 0) s_is64 = sniff_is64(idx);
    __syncthreads();
    long long row = load_index(y, (unsigned)b, s_is64);
    row = row < 0 ? 0 : (row >= n_data ? n_data - 1 : row);

    float v = memory[row * 128 + t] * 0.5f + x[b * 128 + t] * 0.5f;
    float s = v * v;
    #pragma unroll
    for (int off = 16; off; off >>= 1)
        s += __shfl_xor_sync(0xffffffffu, s, off);
    __shared__ float ws[4];
    if ((t & 31) == 0) ws[t >> 5] = s;
    __syncthreads();
    float tot = ws[0] + ws[1] + ws[2] + ws[3];
    float denom = fmaxf(sqrtf(tot), 1e-12f);
    out_mem[row * 128 + t] = v / denom;
    if (b == 0 && t < label_elems) out_labels[t] = 0.0f;
}

// ---------------------------------------------------------------------------
extern "C" void kernel_launch(void* const* d_in, const int* in_sizes, int n_in,
                              void* d_out, int out_size) {
    const float* x      = (const float*)d_in[0];   // [bsz, 128]
    const void*  y      = d_in[1];                 // [bsz]
    const void*  idx    = d_in[2];                 // [bsz, K+1]
    const float* memory = (const float*)d_in[3];   // [n_data, 128]

    int bsz = in_sizes[1];
    unsigned Kp1 = (unsigned)(in_sizes[2] / bsz);
    long long mem_elems = (long long)in_sizes[3];
    long long n_data = mem_elems / 128;
    long long logits_elems = (long long)bsz * Kp1;

    float* out = (float*)d_out;
    long long mem_off = (long long)out_size - mem_elems;
    if (mem_off < logits_elems) mem_off = logits_elems;
    float* out_mem = out + mem_off;
    float* out_labels = out + logits_elems;
    int label_elems = (int)(mem_off - logits_elems);

    if (n_data <= MAX_ROWS && bsz <= 256) {
        unsigned total = (unsigned)logits_elems;
        build_kernel<<<(total + 255) / 256, 256>>>(x, y, idx, memory, out,
                                                   out_labels, label_elems,
                                                   bsz, Kp1, n_data);
        sweep_kernel<<<2048, 256>>>(x, (const float4*)memory,
                                    (float4*)out_mem, out, bsz, Kp1, n_data);
    } else {
        copy_mem_kernel<<<2048, 256>>>((const float4*)memory,
                                       (float4*)out_mem, mem_elems / 4);
        logits_kernel<<<1184, 256>>>(x, y, idx, memory, out,
                                     bsz, Kp1, n_data);
        update_kernel<<<bsz, 128>>>(x, y, idx, memory, out_mem, out_labels,
                                    label_elems, n_data);
    }
}

// round 7
// speedup vs baseline: 1.1248x; 1.1248x over previous
#include <cuda_runtime.h>
#include <stdint.h>

// RGBMem: inverted-index single-sweep, fully fused (2 launches).
//   logits[b,k] = dot(memory[row(b,k)], x[b]) / T,  row(b,0)=y[b], else idx[b,k]
//   labels = zeros
//   new_memory = memory with rows y[b] := normalize(0.5*memory[y]+0.5*x[b])
// Output (float32): [logits (bsz*Kp1)] [labels gap] [memory (n_data*128)]
// build: row->slot inverted lists (+b packed) + update flag in meta.y.
// sweep: ONE streaming pass: copy/EMA each row + all its dot products.
// Meta self-cleans (lane0 8B store) so graph replays see a zeroed state.

#define T_INV (1.0f / 0.07f)
#define MAX_ROWS 524288
#define CAP 16

__device__ uint2 g_meta[MAX_ROWS];                   // .x=count, .y=upd flag
__device__ unsigned g_list[(size_t)MAX_ROWS * CAP];  // 32 MB scratch

__device__ __forceinline__ long long load_index(const void* p, unsigned i,
                                                int is64) {
    if (is64) return ((const long long*)p)[i];
    return (long long)((const int*)p)[i];
}

__device__ __forceinline__ int sniff_is64(const void* idx) {
    const unsigned* w = (const unsigned*)idx;
    int is64 = 1;
    #pragma unroll
    for (int i = 0; i < 16; i++)
        if (w[2 * i + 1] != 0u) { is64 = 0; break; }
    return is64;
}

// ---------------------------------------------------------------------------
// Build: inverted lists (entry = (b<<24)|i), update flags, labels zeroing.
// ---------------------------------------------------------------------------
__global__ void build_kernel(const float* __restrict__ x,
                             const void* __restrict__ y,
                             const void* __restrict__ idx,
                             const float* __restrict__ memory,
                             float* __restrict__ logits,
                             float* __restrict__ out_labels, int label_elems,
                             int bsz, unsigned Kp1, long long n_data) {
    __shared__ int s_is64;
    if (threadIdx.x == 0) s_is64 = sniff_is64(idx);
    __syncthreads();
    int is64 = s_is64;

    if (blockIdx.x == 0) {
        // update flags: max-b wins == "last write wins" for duplicate y
        if (threadIdx.x < (unsigned)bsz) {
            long long r = load_index(y, threadIdx.x, is64);
            r = r < 0 ? 0 : (r >= n_data ? n_data - 1 : r);
            atomicMax(&g_meta[r].y, threadIdx.x + 1u);
        }
        for (int t = threadIdx.x; t < label_elems; t += blockDim.x)
            out_labels[t] = 0.0f;
    }

    unsigned total = (unsigned)bsz * Kp1;
    unsigned i = blockIdx.x * blockDim.x + threadIdx.x;
    unsigned stride = gridDim.x * blockDim.x;
    for (; i < total; i += stride) {
        unsigned b = i / Kp1;
        unsigned k = i - b * Kp1;
        long long row = (k == 0) ? load_index(y, b, is64)
                                 : load_index(idx, i, is64);
        row = row < 0 ? 0 : (row >= n_data ? n_data - 1 : row);
        unsigned p = atomicAdd(&g_meta[row].x, 1u);
        if (p < CAP) {
            g_list[(size_t)row * CAP + p] = (b << 24) | i;
        } else {
            // direct fallback (Poisson tail, ~never; keeps CAP safe)
            const float* mr = memory + row * 128;
            const float* xr = x + b * 128;
            float s = 0.0f;
            for (int d = 0; d < 128; d++) s += __ldg(mr + d) * __ldg(xr + d);
            logits[i] = s * T_INV;
        }
    }
}

// ---------------------------------------------------------------------------
// Sweep: one warp per row (lean, high occupancy). Copy or EMA-update the
// row, compute its logits while resident in registers. Self-clean meta.
// ---------------------------------------------------------------------------
__global__ void __launch_bounds__(256) sweep_kernel(
    const float* __restrict__ x,
    const float4* __restrict__ mem4,
    float4* __restrict__ out_mem4,
    float* __restrict__ logits,
    long long n_data) {
    __shared__ float4 xs[16 * 32];
    int tid = threadIdx.x;
    for (int i = tid; i < 16 * 32; i += blockDim.x)
        xs[i] = ((const float4*)x)[i];
    __syncthreads();

    int lane = tid & 31;
    long long warp = ((long long)blockIdx.x * blockDim.x + tid) >> 5;
    long long nwarps = ((long long)gridDim.x * blockDim.x) >> 5;

    for (long long r = warp; r < n_data; r += nwarps) {
        float4 m = __ldcs(mem4 + r * 32 + lane);   // 512B row, read once
        uint2 meta = g_meta[r];                    // 8B broadcast load

        // ---- logits from ORIGINAL row data ----
        unsigned c = meta.x > CAP ? CAP : meta.x;
        const unsigned* lst = g_list + (size_t)r * CAP;
        for (unsigned e = 0; e < c; e++) {
            unsigned ent = lst[e];                 // broadcast load
            unsigned b = ent >> 24;
            unsigned i = ent & 0xFFFFFFu;
            float4 xv = xs[b * 32 + lane];
            float s = m.x * xv.x + m.y * xv.y + m.z * xv.z + m.w * xv.w;
            #pragma unroll
            for (int off = 16; off; off >>= 1)
                s += __shfl_xor_sync(0xffffffffu, s, off);
            if (lane == 0) logits[i] = s * T_INV;
        }

        // ---- copy out, or EMA+normalize if flagged ----
        if (meta.y == 0) {
            __stcs(out_mem4 + r * 32 + lane, m);
        } else {
            unsigned b = meta.y - 1u;
            float4 xv = xs[b * 32 + lane];
            float4 v;
            v.x = 0.5f * m.x + 0.5f * xv.x;
            v.y = 0.5f * m.y + 0.5f * xv.y;
            v.z = 0.5f * m.z + 0.5f * xv.z;
            v.w = 0.5f * m.w + 0.5f * xv.w;
            float s = v.x * v.x + v.y * v.y + v.z * v.z + v.w * v.w;
            #pragma unroll
            for (int off = 16; off; off >>= 1)
                s += __shfl_xor_sync(0xffffffffu, s, off);
            float inv = 1.0f / fmaxf(sqrtf(s), 1e-12f);
            v.x *= inv; v.y *= inv; v.z *= inv; v.w *= inv;
            __stcs(out_mem4 + r * 32 + lane, v);
        }

        // ---- self-clean for next graph replay (one 8B store) ----
        if (lane == 0) g_meta[r] = make_uint2(0u, 0u);
    }
}

// ---------------------------------------------------------------------------
// Fallback path (n_data > MAX_ROWS or bsz > 256): R2-proven kernels.
// ---------------------------------------------------------------------------
__global__ void copy_mem_kernel(const float4* __restrict__ src,
                                float4* __restrict__ dst, long long n4) {
    long long i = (long long)blockIdx.x * blockDim.x + threadIdx.x;
    long long stride = (long long)gridDim.x * blockDim.x;
    for (; i < n4; i += stride) dst[i] = src[i];
}

__global__ void logits_kernel(const float* __restrict__ x,
                              const void* __restrict__ y,
                              const void* __restrict__ idx,
                              const float* __restrict__ memory,
                              float* __restrict__ logits,
                              int bsz, unsigned Kp1, long long n_data) {
    __shared__ float4 xs[16 * 32];
    __shared__ int s_is64;
    int tid = threadIdx.x;
    if (tid == 0) s_is64 = sniff_is64(idx);
    int nx4 = bsz * 32;
    for (int i = tid; i < nx4; i += blockDim.x) xs[i] = ((const float4*)x)[i];
    __syncthreads();
    int is64 = s_is64;

    int lane = tid & 31;
    unsigned warp = (blockIdx.x * blockDim.x + tid) >> 5;
    unsigned nwarps = (gridDim.x * blockDim.x) >> 5;
    unsigned total = (unsigned)bsz * Kp1;

    for (unsigned i = warp; i < total; i += nwarps) {
        unsigned b = i / Kp1;
        unsigned k = i - b * Kp1;
        long long row = (k == 0) ? load_index(y, b, is64)
                                 : load_index(idx, i, is64);
        row = row < 0 ? 0 : (row >= n_data ? n_data - 1 : row);
        float4 mm = __ldg((const float4*)(memory + row * 128) + lane);
        float4 xv = xs[b * 32 + lane];
        float s = mm.x * xv.x + mm.y * xv.y + mm.z * xv.z + mm.w * xv.w;
        #pragma unroll
        for (int off = 16; off; off >>= 1)
            s += __shfl_xor_sync(0xffffffffu, s, off);
        if (lane == 0) logits[i] = s * T_INV;
    }
}

__global__ void update_kernel(const float* __restrict__ x,
                              const void* __restrict__ y,
                              const void* __restrict__ idx,
                              const float* __restrict__ memory,
                              float* __restrict__ out_mem,
                              float* __restrict__ out_labels,
                              int label_elems, long long n_data) {
    int b = blockIdx.x;
    int t = threadIdx.x;
    __shared__ int s_is64;
    if (t == 0) s_is64 = sniff_is64(idx);
    __syncthreads();
    long long row = load_index(y, (unsigned)b, s_is64);
    row = row < 0 ? 0 : (row >= n_data ? n_data - 1 : row);

    float v = memory[row * 128 + t] * 0.5f + x[b * 128 + t] * 0.5f;
    float s = v * v;
    #pragma unroll
    for (int off = 16; off; off >>= 1)
        s += __shfl_xor_sync(0xffffffffu, s, off);
    __shared__ float ws[4];
    if ((t & 31) == 0) ws[t >> 5] = s;
    __syncthreads();
    float tot = ws[0] + ws[1] + ws[2] + ws[3];
    float denom = fmaxf(sqrtf(tot), 1e-12f);
    out_mem[row * 128 + t] = v / denom;
    if (b == 0 && t < label_elems) out_labels[t] = 0.0f;
}

// ---------------------------------------------------------------------------
extern "C" void kernel_launch(void* const* d_in, const int* in_sizes, int n_in,
                              void* d_out, int out_size) {
    const float* x      = (const float*)d_in[0];   // [bsz, 128]
    const void*  y      = d_in[1];                 // [bsz]
    const void*  idx    = d_in[2];                 // [bsz, K+1]
    const float* memory = (const float*)d_in[3];   // [n_data, 128]

    int bsz = in_sizes[1];
    unsigned Kp1 = (unsigned)(in_sizes[2] / bsz);
    long long mem_elems = (long long)in_sizes[3];
    long long n_data = mem_elems / 128;
    long long logits_elems = (long long)bsz * Kp1;

    float* out = (float*)d_out;
    long long mem_off = (long long)out_size - mem_elems;
    if (mem_off < logits_elems) mem_off = logits_elems;
    float* out_mem = out + mem_off;
    float* out_labels = out + logits_elems;
    int label_elems = (int)(mem_off - logits_elems);

    // packed-entry encoding needs i < 2^24 and b < 256
    if (n_data <= MAX_ROWS && bsz <= 16 && logits_elems < (1 << 24)) {
        unsigned total = (unsigned)logits_elems;
        build_kernel<<<(total + 255) / 256, 256>>>(x, y, idx, memory, out,
                                                   out_labels, label_elems,
                                                   bsz, Kp1, n_data);
        sweep_kernel<<<2048, 256>>>(x, (const float4*)memory,
                                    (float4*)out_mem, out, n_data);
    } else {
        copy_mem_kernel<<<2048, 256>>>((const float4*)memory,
                                       (float4*)out_mem, mem_elems / 4);
        logits_kernel<<<1184, 256>>>(x, y, idx, memory, out,
                                     bsz, Kp1, n_data);
        update_kernel<<<bsz, 128>>>(x, y, idx, memory, out_mem, out_labels,
                                    label_elems, n_data);
    }
}

// round 10
// speedup vs baseline: 1.4240x; 1.2660x over previous
#include <cuda_runtime.h>
#include <stdint.h>

// RGBMem: inverted-index single-sweep, fully fused (2 launches).
//   logits[b,k] = dot(memory[row(b,k)], x[b]) / T,  row(b,0)=y[b], else idx[b,k]
//   labels = zeros
//   new_memory = memory with rows y[b] := normalize(0.5*memory[y]+0.5*x[b])
// Output (float32): [logits (bsz*Kp1)] [labels gap] [memory (n_data*128)]
// sweep: each warp handles TWO consecutive rows, one per 16-lane half; the
// width-16 butterfly reduction serves both rows with one instruction stream.
// FIX vs R8: divergent EMA-path shuffles now use the per-half member mask
// (0xFFFF << 16*half) -- full-warp mask under half-warp divergence hangs.

#define T_INV (1.0f / 0.07f)
#define MAX_ROWS 524288
#define CAP 16

__device__ uint2 g_meta[MAX_ROWS];                   // .x=count, .y=upd flag
__device__ unsigned g_list[(size_t)MAX_ROWS * CAP];  // 32 MB scratch

__device__ __forceinline__ long long load_index(const void* p, unsigned i,
                                                int is64) {
    if (is64) return ((const long long*)p)[i];
    return (long long)((const int*)p)[i];
}

__device__ __forceinline__ int sniff_is64(const void* idx) {
    const unsigned* w = (const unsigned*)idx;
    int is64 = 1;
    #pragma unroll
    for (int i = 0; i < 16; i++)
        if (w[2 * i + 1] != 0u) { is64 = 0; break; }
    return is64;
}

// ---------------------------------------------------------------------------
// Build: inverted lists (entry = (b<<24)|i), update flags, labels zeroing.
// ---------------------------------------------------------------------------
__global__ void build_kernel(const float* __restrict__ x,
                             const void* __restrict__ y,
                             const void* __restrict__ idx,
                             const float* __restrict__ memory,
                             float* __restrict__ logits,
                             float* __restrict__ out_labels, int label_elems,
                             int bsz, unsigned Kp1, long long n_data) {
    __shared__ int s_is64;
    if (threadIdx.x == 0) s_is64 = sniff_is64(idx);
    __syncthreads();
    int is64 = s_is64;

    if (blockIdx.x == 0) {
        if (threadIdx.x < (unsigned)bsz) {
            long long r = load_index(y, threadIdx.x, is64);
            r = r < 0 ? 0 : (r >= n_data ? n_data - 1 : r);
            atomicMax(&g_meta[r].y, threadIdx.x + 1u);   // last-write-wins
        }
        for (int t = threadIdx.x; t < label_elems; t += blockDim.x)
            out_labels[t] = 0.0f;
    }

    unsigned total = (unsigned)bsz * Kp1;
    unsigned i = blockIdx.x * blockDim.x + threadIdx.x;
    unsigned stride = gridDim.x * blockDim.x;
    for (; i < total; i += stride) {
        unsigned b = i / Kp1;
        unsigned k = i - b * Kp1;
        long long row = (k == 0) ? load_index(y, b, is64)
                                 : load_index(idx, i, is64);
        row = row < 0 ? 0 : (row >= n_data ? n_data - 1 : row);
        unsigned p = atomicAdd(&g_meta[row].x, 1u);
        if (p < CAP) {
            g_list[(size_t)row * CAP + p] = (b << 24) | i;
        } else {
            // direct fallback (Poisson tail, ~never; keeps CAP safe)
            const float* mr = memory + row * 128;
            const float* xr = x + b * 128;
            float s = 0.0f;
            for (int d = 0; d < 128; d++) s += __ldg(mr + d) * __ldg(xr + d);
            logits[i] = s * T_INV;
        }
    }
}

// ---------------------------------------------------------------------------
// Sweep: 2 rows per warp, one per 16-lane half. Lane covers 8 floats of its
// row. Width-16 butterfly (4 steps) reduces both rows at once.
// ---------------------------------------------------------------------------
__global__ void __launch_bounds__(256) sweep_kernel(
    const float* __restrict__ x,
    const float4* __restrict__ mem4,
    float4* __restrict__ out_mem4,
    float* __restrict__ logits,
    unsigned n_data) {
    __shared__ float4 xs[16 * 32];
    int tid = threadIdx.x;
    for (int i = tid; i < 16 * 32; i += blockDim.x)
        xs[i] = ((const float4*)x)[i];
    __syncthreads();

    unsigned lane = tid & 31u;
    unsigned half = lane >> 4;                    // which row of the pair
    unsigned hl = lane & 15u;                     // lane within half
    unsigned hmask = 0xFFFFu << (half * 16u);     // member mask of this half
    unsigned warp = ((unsigned)blockIdx.x * blockDim.x + tid) >> 5;
    unsigned nwarps = ((unsigned)gridDim.x * blockDim.x) >> 5;

    for (unsigned rb = warp * 2u; rb < n_data; rb += nwarps * 2u) {
        unsigned r = rb + half;
        bool valid = r < n_data;
        unsigned rs = valid ? r : (n_data - 1u);

        // full 512B row per half: 2 float4 per lane (warp = 1KB contiguous)
        float4 m0 = __ldcs(mem4 + rs * 32u + hl);
        float4 m1 = __ldcs(mem4 + rs * 32u + hl + 16u);
        uint2 meta = g_meta[rs];
        unsigned c = valid ? (meta.x > CAP ? CAP : meta.x) : 0u;
        unsigned upd = valid ? meta.y : 0u;

        unsigned co = __shfl_xor_sync(0xffffffffu, c, 16);
        unsigned cmax = c > co ? c : co;          // warp-uniform

        const unsigned* lst = g_list + rs * (unsigned)CAP;
        for (unsigned e = 0; e < cmax; e++) {     // all 32 lanes iterate
            bool act = e < c;
            unsigned ent = act ? lst[e] : 0u;     // broadcast within half
            unsigned b = ent >> 24;
            unsigned i = ent & 0xFFFFFFu;
            float4 xv0 = xs[b * 32u + hl];
            float4 xv1 = xs[b * 32u + hl + 16u];
            float s = m0.x * xv0.x + m0.y * xv0.y + m0.z * xv0.z +
                      m0.w * xv0.w + m1.x * xv1.x + m1.y * xv1.y +
                      m1.z * xv1.z + m1.w * xv1.w;
            #pragma unroll
            for (int off = 8; off; off >>= 1)     // uniform: full mask OK
                s += __shfl_xor_sync(0xffffffffu, s, off);
            if (act && hl == 0) logits[i] = s * T_INV;
        }

        if (valid) {
            if (upd == 0) {
                __stcs(out_mem4 + r * 32u + hl, m0);
                __stcs(out_mem4 + r * 32u + hl + 16u, m1);
            } else {
                // divergent within warp: use per-half mask shuffles only
                unsigned b = upd - 1u;
                float4 xv0 = xs[b * 32u + hl];
                float4 xv1 = xs[b * 32u + hl + 16u];
                float4 v0, v1;
                v0.x = 0.5f * (m0.x + xv0.x); v0.y = 0.5f * (m0.y + xv0.y);
                v0.z = 0.5f * (m0.z + xv0.z); v0.w = 0.5f * (m0.w + xv0.w);
                v1.x = 0.5f * (m1.x + xv1.x); v1.y = 0.5f * (m1.y + xv1.y);
                v1.z = 0.5f * (m1.z + xv1.z); v1.w = 0.5f * (m1.w + xv1.w);
                float s = v0.x * v0.x + v0.y * v0.y + v0.z * v0.z +
                          v0.w * v0.w + v1.x * v1.x + v1.y * v1.y +
                          v1.z * v1.z + v1.w * v1.w;
                #pragma unroll
                for (int off = 8; off; off >>= 1)
                    s += __shfl_xor_sync(hmask, s, off);
                float inv = 1.0f / fmaxf(sqrtf(s), 1e-12f);
                v0.x *= inv; v0.y *= inv; v0.z *= inv; v0.w *= inv;
                v1.x *= inv; v1.y *= inv; v1.z *= inv; v1.w *= inv;
                __stcs(out_mem4 + r * 32u + hl, v0);
                __stcs(out_mem4 + r * 32u + hl + 16u, v1);
            }
            if (hl == 0) g_meta[r] = make_uint2(0u, 0u);  // self-clean
        }
    }
}

// ---------------------------------------------------------------------------
// Fallback path (shape out of range): R2-proven kernels.
// ---------------------------------------------------------------------------
__global__ void copy_mem_kernel(const float4* __restrict__ src,
                                float4* __restrict__ dst, long long n4) {
    long long i = (long long)blockIdx.x * blockDim.x + threadIdx.x;
    long long stride = (long long)gridDim.x * blockDim.x;
    for (; i < n4; i += stride) dst[i] = src[i];
}

__global__ void logits_kernel(const float* __restrict__ x,
                              const void* __restrict__ y,
                              const void* __restrict__ idx,
                              const float* __restrict__ memory,
                              float* __restrict__ logits,
                              int bsz, unsigned Kp1, long long n_data) {
    __shared__ float4 xs[16 * 32];
    __shared__ int s_is64;
    int tid = threadIdx.x;
    if (tid == 0) s_is64 = sniff_is64(idx);
    int nx4 = bsz * 32;
    for (int i = tid; i < nx4; i += blockDim.x) xs[i] = ((const float4*)x)[i];
    __syncthreads();
    int is64 = s_is64;

    int lane = tid & 31;
    unsigned warp = (blockIdx.x * blockDim.x + tid) >> 5;
    unsigned nwarps = (gridDim.x * blockDim.x) >> 5;
    unsigned total = (unsigned)bsz * Kp1;

    for (unsigned i = warp; i < total; i += nwarps) {
        unsigned b = i / Kp1;
        unsigned k = i - b * Kp1;
        long long row = (k == 0) ? load_index(y, b, is64)
                                 : load_index(idx, i, is64);
        row = row < 0 ? 0 : (row >= n_data ? n_data - 1 : row);
        float4 mm = __ldg((const float4*)(memory + row * 128) + lane);
        float4 xv = xs[b * 32 + lane];
        float s = mm.x * xv.x + mm.y * xv.y + mm.z * xv.z + mm.w * xv.w;
        #pragma unroll
        for (int off = 16; off; off >>= 1)
            s += __shfl_xor_sync(0xffffffffu, s, off);
        if (lane == 0) logits[i] = s * T_INV;
    }
}

__global__ void update_kernel(const float* __restrict__ x,
                              const void* __restrict__ y,
                              const void* __restrict__ idx,
                              const float* __restrict__ memory,
                              float* __restrict__ out_mem,
                              float* __restrict__ out_labels,
                              int label_elems, long long n_data) {
    int b = blockIdx.x;
    int t = threadIdx.x;
    __shared__ int s_is64;
    if (t == 0) s_is64 = sniff_is64(idx);
    __syncthreads();
    long long row = load_index(y, (unsigned)b, s_is64);
    row = row < 0 ? 0 : (row >= n_data ? n_data - 1 : row);

    float v = memory[row * 128 + t] * 0.5f + x[b * 128 + t] * 0.5f;
    float s = v * v;
    #pragma unroll
    for (int off = 16; off; off >>= 1)
        s += __shfl_xor_sync(0xffffffffu, s, off);
    __shared__ float ws[4];
    if ((t & 31) == 0) ws[t >> 5] = s;
    __syncthreads();
    float tot = ws[0] + ws[1] + ws[2] + ws[3];
    float denom = fmaxf(sqrtf(tot), 1e-12f);
    out_mem[row * 128 + t] = v / denom;
    if (b == 0 && t < label_elems) out_labels[t] = 0.0f;
}

// ---------------------------------------------------------------------------
extern "C" void kernel_launch(void* const* d_in, const int* in_sizes, int n_in,
                              void* d_out, int out_size) {
    const float* x      = (const float*)d_in[0];   // [bsz, 128]
    const void*  y      = d_in[1];                 // [bsz]
    const void*  idx    = d_in[2];                 // [bsz, K+1]
    const float* memory = (const float*)d_in[3];   // [n_data, 128]

    int bsz = in_sizes[1];
    unsigned Kp1 = (unsigned)(in_sizes[2] / bsz);
    long long mem_elems = (long long)in_sizes[3];
    long long n_data = mem_elems / 128;
    long long logits_elems = (long long)bsz * Kp1;

    float* out = (float*)d_out;
    long long mem_off = (long long)out_size - mem_elems;
    if (mem_off < logits_elems) mem_off = logits_elems;
    float* out_mem = out + mem_off;
    float* out_labels = out + logits_elems;
    int label_elems = (int)(mem_off - logits_elems);

    if (n_data <= MAX_ROWS && bsz <= 16 && logits_elems < (1 << 24)) {
        unsigned total = (unsigned)logits_elems;
        build_kernel<<<(total + 255) / 256, 256>>>(x, y, idx, memory, out,
                                                   out_labels, label_elems,
                                                   bsz, Kp1, n_data);
        sweep_kernel<<<2048, 256>>>(x, (const float4*)memory,
                                    (float4*)out_mem, out,
                                    (unsigned)n_data);
    } else {
        copy_mem_kernel<<<2048, 256>>>((const float4*)memory,
                                       (float4*)out_mem, mem_elems / 4);
        logits_kernel<<<1184, 256>>>(x, y, idx, memory, out,
                                     bsz, Kp1, n_data);
        update_kernel<<<bsz, 128>>>(x, y, idx, memory, out_mem, out_labels,
                                    label_elems, n_data);
    }
}

// round 13
// speedup vs baseline: 1.4410x; 1.0119x over previous
#include <cuda_runtime.h>
#include <stdint.h>

// RGBMem: inverted-index single-sweep, fully fused (2 launches).
//   logits[b,k] = dot(memory[row(b,k)], x[b]) / T,  row(b,0)=y[b], else idx[b,k]
//   labels = zeros
//   new_memory = memory with rows y[b] := normalize(0.5*memory[y]+0.5*x[b])
// Output (float32): [logits (bsz*Kp1)] [labels gap] [memory (n_data*128)]
// sweep: 2 rows/warp (16-lane halves), packed f32x2 FMA (FFMA2 via PTX),
// uint4 list prefetch. Meta self-cleans for graph replays.

#define T_INV (1.0f / 0.07f)
#define MAX_ROWS 524288
#define CAP 16

__device__ uint2 g_meta[MAX_ROWS];                   // .x=count, .y=upd flag
__device__ unsigned g_list[(size_t)MAX_ROWS * CAP];  // 32 MB scratch

__device__ __forceinline__ long long load_index(const void* p, unsigned i,
                                                int is64) {
    if (is64) return ((const long long*)p)[i];
    return (long long)((const int*)p)[i];
}

__device__ __forceinline__ int sniff_is64(const void* idx) {
    const unsigned* w = (const unsigned*)idx;
    int is64 = 1;
    #pragma unroll
    for (int i = 0; i < 16; i++)
        if (w[2 * i + 1] != 0u) { is64 = 0; break; }
    return is64;
}

// packed f32x2 helpers (FFMA2 is PTX-only; ptxas never auto-fuses)
__device__ __forceinline__ unsigned long long f2fma(
    unsigned long long a, unsigned long long b, unsigned long long c) {
    unsigned long long d;
    asm("fma.rn.f32x2 %0, %1, %2, %3;" : "=l"(d) : "l"(a), "l"(b), "l"(c));
    return d;
}
__device__ __forceinline__ void f2unpack(unsigned long long v,
                                         float& lo, float& hi) {
    asm("mov.b64 {%0, %1}, %2;" : "=f"(lo), "=f"(hi) : "l"(v));
}

// ---------------------------------------------------------------------------
// Build: inverted lists (entry = (b<<24)|i), update flags, labels zeroing.
// ---------------------------------------------------------------------------
__global__ void build_kernel(const float* __restrict__ x,
                             const void* __restrict__ y,
                             const void* __restrict__ idx,
                             const float* __restrict__ memory,
                             float* __restrict__ logits,
                             float* __restrict__ out_labels, int label_elems,
                             int bsz, unsigned Kp1, long long n_data) {
    __shared__ int s_is64;
    if (threadIdx.x == 0) s_is64 = sniff_is64(idx);
    __syncthreads();
    int is64 = s_is64;

    if (blockIdx.x == 0) {
        if (threadIdx.x < (unsigned)bsz) {
            long long r = load_index(y, threadIdx.x, is64);
            r = r < 0 ? 0 : (r >= n_data ? n_data - 1 : r);
            atomicMax(&g_meta[r].y, threadIdx.x + 1u);   // last-write-wins
        }
        for (int t = threadIdx.x; t < label_elems; t += blockDim.x)
            out_labels[t] = 0.0f;
    }

    unsigned total = (unsigned)bsz * Kp1;
    unsigned i = blockIdx.x * blockDim.x + threadIdx.x;
    unsigned stride = gridDim.x * blockDim.x;
    for (; i < total; i += stride) {
        unsigned b = i / Kp1;
        unsigned k = i - b * Kp1;
        long long row = (k == 0) ? load_index(y, b, is64)
                                 : load_index(idx, i, is64);
        row = row < 0 ? 0 : (row >= n_data ? n_data - 1 : row);
        unsigned p = atomicAdd(&g_meta[row].x, 1u);
        if (p < CAP) {
            g_list[(size_t)row * CAP + p] = (b << 24) | i;
        } else {
            // direct fallback (Poisson tail, ~never; keeps CAP safe)
            const float* mr = memory + row * 128;
            const float* xr = x + b * 128;
            float s = 0.0f;
            for (int d = 0; d < 128; d++) s += __ldg(mr + d) * __ldg(xr + d);
            logits[i] = s * T_INV;
        }
    }
}

// ---------------------------------------------------------------------------
// Sweep: 2 rows per warp, one per 16-lane half; lane holds 8 floats of its
// row as 4 packed-f32x2 regs. Width-16 butterfly serves both rows at once.
// ---------------------------------------------------------------------------
__global__ void __launch_bounds__(256) sweep_kernel(
    const float* __restrict__ x,
    const double2* __restrict__ mem2,
    float4* __restrict__ out_mem4,
    float* __restrict__ logits,
    unsigned n_data) {
    __shared__ double2 xs[16 * 32];      // x as packed f32x2 pairs
    int tid = threadIdx.x;
    for (int i = tid; i < 16 * 32; i += blockDim.x)
        xs[i] = ((const double2*)x)[i];
    __syncthreads();

    unsigned lane = tid & 31u;
    unsigned half = lane >> 4;
    unsigned hl = lane & 15u;
    unsigned hmask = 0xFFFFu << (half * 16u);
    unsigned warp = ((unsigned)blockIdx.x * blockDim.x + tid) >> 5;
    unsigned nwarps = ((unsigned)gridDim.x * blockDim.x) >> 5;

    for (unsigned rb = warp * 2u; rb < n_data; rb += nwarps * 2u) {
        unsigned r = rb + half;
        bool valid = r < n_data;
        unsigned rs = valid ? r : (n_data - 1u);

        double2 a0 = __ldcs(mem2 + rs * 32u + hl);        // 16B chunk
        double2 a1 = __ldcs(mem2 + rs * 32u + hl + 16u);  // 16B chunk
        uint2 meta = g_meta[rs];
        unsigned c = valid ? (meta.x > CAP ? CAP : meta.x) : 0u;
        unsigned upd = valid ? meta.y : 0u;

        unsigned long long ma0 = __double_as_longlong(a0.x);
        unsigned long long ma1 = __double_as_longlong(a0.y);
        unsigned long long ma2 = __double_as_longlong(a1.x);
        unsigned long long ma3 = __double_as_longlong(a1.y);

        unsigned co = __shfl_xor_sync(0xffffffffu, c, 16);
        unsigned cmax = c > co ? c : co;      // warp-uniform

        const uint4* lst4 = (const uint4*)(g_list + (size_t)rs * CAP);
        for (unsigned base = 0; base < cmax; base += 4u) {
            uint4 L = lst4[base >> 2];        // 4 entries in one LDG.128
            #pragma unroll
            for (int j = 0; j < 4; j++) {
                unsigned e = base + (unsigned)j;
                if (e >= cmax) break;         // warp-uniform exit
                bool act = e < c;
                unsigned ent = (j == 0) ? L.x : (j == 1) ? L.y
                             : (j == 2) ? L.z : L.w;
                unsigned b = (ent >> 24) & 15u;   // mask: garbage-safe
                unsigned i = ent & 0xFFFFFFu;
                const double2 xv0 = xs[b * 32u + hl];
                const double2 xv1 = xs[b * 32u + hl + 16u];
                unsigned long long acc =
                    f2fma(ma0, __double_as_longlong(xv0.x), 0ull);
                acc = f2fma(ma1, __double_as_longlong(xv0.y), acc);
                acc = f2fma(ma2, __double_as_longlong(xv1.x), acc);
                acc = f2fma(ma3, __double_as_longlong(xv1.y), acc);
                float lo, hi;
                f2unpack(acc, lo, hi);
                float s = lo + hi;
                #pragma unroll
                for (int off = 8; off; off >>= 1)   // uniform: full mask OK
                    s += __shfl_xor_sync(0xffffffffu, s, off);
                if (act && hl == 0) logits[i] = s * T_INV;
            }
        }

        if (valid) {
            if (upd == 0) {
                float4* dst = out_mem4 + r * 32u;
                __stcs(dst + hl, *(const float4*)&a0);
                __stcs(dst + hl + 16u, *(const float4*)&a1);
            } else {
                // cold path, divergent within warp: per-half mask shuffles
                unsigned b = upd - 1u;
                float m0x, m0y, m0z, m0w, m1x, m1y, m1z, m1w;
                f2unpack(ma0, m0x, m0y); f2unpack(ma1, m0z, m0w);
                f2unpack(ma2, m1x, m1y); f2unpack(ma3, m1z, m1w);
                const float4* xf = (const float4*)xs;
                float4 xv0 = xf[b * 32u + hl];
                float4 xv1 = xf[b * 32u + hl + 16u];
                float4 v0, v1;
                v0.x = 0.5f * (m0x + xv0.x); v0.y = 0.5f * (m0y + xv0.y);
                v0.z = 0.5f * (m0z + xv0.z); v0.w = 0.5f * (m0w + xv0.w);
                v1.x = 0.5f * (m1x + xv1.x); v1.y = 0.5f * (m1y + xv1.y);
                v1.z = 0.5f * (m1z + xv1.z); v1.w = 0.5f * (m1w + xv1.w);
                float s = v0.x * v0.x + v0.y * v0.y + v0.z * v0.z +
                          v0.w * v0.w + v1.x * v1.x + v1.y * v1.y +
                          v1.z * v1.z + v1.w * v1.w;
                #pragma unroll
                for (int off = 8; off; off >>= 1)
                    s += __shfl_xor_sync(hmask, s, off);
                float inv = 1.0f / fmaxf(sqrtf(s), 1e-12f);
                v0.x *= inv; v0.y *= inv; v0.z *= inv; v0.w *= inv;
                v1.x *= inv; v1.y *= inv; v1.z *= inv; v1.w *= inv;
                float4* dst = out_mem4 + r * 32u;
                __stcs(dst + hl, v0);
                __stcs(dst + hl + 16u, v1);
            }
            if (hl == 0) g_meta[r] = make_uint2(0u, 0u);  // self-clean
        }
    }
}

// ---------------------------------------------------------------------------
// Fallback path (shape out of range): R2-proven kernels.
// ---------------------------------------------------------------------------
__global__ void copy_mem_kernel(const float4* __restrict__ src,
                                float4* __restrict__ dst, long long n4) {
    long long i = (long long)blockIdx.x * blockDim.x + threadIdx.x;
    long long stride = (long long)gridDim.x * blockDim.x;
    for (; i < n4; i += stride) dst[i] = src[i];
}

__global__ void logits_kernel(const float* __restrict__ x,
                              const void* __restrict__ y,
                              const void* __restrict__ idx,
                              const float* __restrict__ memory,
                              float* __restrict__ logits,
                              int bsz, unsigned Kp1, long long n_data) {
    __shared__ float4 xs[16 * 32];
    __shared__ int s_is64;
    int tid = threadIdx.x;
    if (tid == 0) s_is64 = sniff_is64(idx);
    int nx4 = bsz * 32;
    for (int i = tid; i < nx4; i += blockDim.x) xs[i] = ((const float4*)x)[i];
    __syncthreads();
    int is64 = s_is64;

    int lane = tid & 31;
    unsigned warp = (blockIdx.x * blockDim.x + tid) >> 5;
    unsigned nwarps = (gridDim.x * blockDim.x) >> 5;
    unsigned total = (unsigned)bsz * Kp1;

    for (unsigned i = warp; i < total; i += nwarps) {
        unsigned b = i / Kp1;
        unsigned k = i - b * Kp1;
        long long row = (k == 0) ? load_index(y, b, is64)
                                 : load_index(idx, i, is64);
        row = row < 0 ? 0 : (row >= n_data ? n_data - 1 : row);
        float4 mm = __ldg((const float4*)(memory + row * 128) + lane);
        float4 xv = xs[b * 32 + lane];
        float s = mm.x * xv.x + mm.y * xv.y + mm.z * xv.z + mm.w * xv.w;
        #pragma unroll
        for (int off = 16; off; off >>= 1)
            s += __shfl_xor_sync(0xffffffffu, s, off);
        if (lane == 0) logits[i] = s * T_INV;
    }
}

__global__ void update_kernel(const float* __restrict__ x,
                              const void* __restrict__ y,
                              const void* __restrict__ idx,
                              const float* __restrict__ memory,
                              float* __restrict__ out_mem,
                              float* __restrict__ out_labels,
                              int label_elems, long long n_data) {
    int b = blockIdx.x;
    int t = threadIdx.x;
    __shared__ int s_is64;
    if (t == 0) s_is64 = sniff_is64(idx);
    __syncthreads();
    long long row = load_index(y, (unsigned)b, s_is64);
    row = row < 0 ? 0 : (row >= n_data ? n_data - 1 : row);

    float v = memory[row * 128 + t] * 0.5f + x[b * 128 + t] * 0.5f;
    float s = v * v;
    #pragma unroll
    for (int off = 16; off; off >>= 1)
        s += __shfl_xor_sync(0xffffffffu, s, off);
    __shared__ float ws[4];
    if ((t & 31) == 0) ws[t >> 5] = s;
    __syncthreads();
    float tot = ws[0] + ws[1] + ws[2] + ws[3];
    float denom = fmaxf(sqrtf(tot), 1e-12f);
    out_mem[row * 128 + t] = v / denom;
    if (b == 0 && t < label_elems) out_labels[t] = 0.0f;
}

// ---------------------------------------------------------------------------
extern "C" void kernel_launch(void* const* d_in, const int* in_sizes, int n_in,
                              void* d_out, int out_size) {
    const float* x      = (const float*)d_in[0];   // [bsz, 128]
    const void*  y      = d_in[1];                 // [bsz]
    const void*  idx    = d_in[2];                 // [bsz, K+1]
    const float* memory = (const float*)d_in[3];   // [n_data, 128]

    int bsz = in_sizes[1];
    unsigned Kp1 = (unsigned)(in_sizes[2] / bsz);
    long long mem_elems = (long long)in_sizes[3];
    long long n_data = mem_elems / 128;
    long long logits_elems = (long long)bsz * Kp1;

    float* out = (float*)d_out;
    long long mem_off = (long long)out_size - mem_elems;
    if (mem_off < logits_elems) mem_off = logits_elems;
    float* out_mem = out + mem_off;
    float* out_labels = out + logits_elems;
    int label_elems = (int)(mem_off - logits_elems);

    if (n_data <= MAX_ROWS && bsz <= 16 && logits_elems < (1 << 24)) {
        unsigned total = (unsigned)logits_elems;
        build_kernel<<<(total + 255) / 256, 256>>>(x, y, idx, memory, out,
                                                   out_labels, label_elems,
                                                   bsz, Kp1, n_data);
        sweep_kernel<<<2048, 256>>>(x, (const double2*)memory,
                                    (float4*)out_mem, out,
                                    (unsigned)n_data);
    } else {
        copy_mem_kernel<<<2048, 256>>>((const float4*)memory,
                                       (float4*)out_mem, mem_elems / 4);
        logits_kernel<<<1184, 256>>>(x, y, idx, memory, out,
                                     bsz, Kp1, n_data);
        update_kernel<<<bsz, 128>>>(x, y, idx, memory, out_mem, out_labels,
                                    label_elems, n_data);
    }
}

// round 14
// speedup vs baseline: 1.5260x; 1.0590x over previous
#include <cuda_runtime.h>
#include <stdint.h>

// RGBMem: inverted-index single-sweep, fully fused (2 launches).
//   logits[b,k] = dot(memory[row(b,k)], x[b]) / T,  row(b,0)=y[b], else idx[b,k]
//   labels = zeros
//   new_memory = memory with rows y[b] := normalize(0.5*memory[y]+0.5*x[b])
// Output (float32): [logits (bsz*Kp1)] [labels gap] [memory (n_data*128)]
// sweep: 2 rows/warp (16-lane halves), width-16 butterfly serves both rows.
// R14: __launch_bounds__(256,8) forces 32 regs -> 8 blocks/SM (100% occ
// ceiling); R13 showed the kernel is latency-bound at 64.8% occupancy.

#define T_INV (1.0f / 0.07f)
#define MAX_ROWS 524288
#define CAP 16

__device__ uint2 g_meta[MAX_ROWS];                   // .x=count, .y=upd flag
__device__ unsigned g_list[(size_t)MAX_ROWS * CAP];  // 32 MB scratch

__device__ __forceinline__ long long load_index(const void* p, unsigned i,
                                                int is64) {
    if (is64) return ((const long long*)p)[i];
    return (long long)((const int*)p)[i];
}

__device__ __forceinline__ int sniff_is64(const void* idx) {
    const unsigned* w = (const unsigned*)idx;
    int is64 = 1;
    #pragma unroll
    for (int i = 0; i < 16; i++)
        if (w[2 * i + 1] != 0u) { is64 = 0; break; }
    return is64;
}

// ---------------------------------------------------------------------------
// Build: inverted lists (entry = (b<<24)|i), update flags, labels zeroing.
// ---------------------------------------------------------------------------
__global__ void build_kernel(const float* __restrict__ x,
                             const void* __restrict__ y,
                             const void* __restrict__ idx,
                             const float* __restrict__ memory,
                             float* __restrict__ logits,
                             float* __restrict__ out_labels, int label_elems,
                             int bsz, unsigned Kp1, long long n_data) {
    __shared__ int s_is64;
    if (threadIdx.x == 0) s_is64 = sniff_is64(idx);
    __syncthreads();
    int is64 = s_is64;

    if (blockIdx.x == 0) {
        if (threadIdx.x < (unsigned)bsz) {
            long long r = load_index(y, threadIdx.x, is64);
            r = r < 0 ? 0 : (r >= n_data ? n_data - 1 : r);
            atomicMax(&g_meta[r].y, threadIdx.x + 1u);   // last-write-wins
        }
        for (int t = threadIdx.x; t < label_elems; t += blockDim.x)
            out_labels[t] = 0.0f;
    }

    unsigned total = (unsigned)bsz * Kp1;
    unsigned i = blockIdx.x * blockDim.x + threadIdx.x;
    unsigned stride = gridDim.x * blockDim.x;
    for (; i < total; i += stride) {
        unsigned b = i / Kp1;
        unsigned k = i - b * Kp1;
        long long row = (k == 0) ? load_index(y, b, is64)
                                 : load_index(idx, i, is64);
        row = row < 0 ? 0 : (row >= n_data ? n_data - 1 : row);
        unsigned p = atomicAdd(&g_meta[row].x, 1u);
        if (p < CAP) {
            g_list[(size_t)row * CAP + p] = (b << 24) | i;
        } else {
            // direct fallback (Poisson tail, ~never; keeps CAP safe)
            const float* mr = memory + row * 128;
            const float* xr = x + b * 128;
            float s = 0.0f;
            for (int d = 0; d < 128; d++) s += __ldg(mr + d) * __ldg(xr + d);
            logits[i] = s * T_INV;
        }
    }
}

// ---------------------------------------------------------------------------
// Sweep: 2 rows per warp, one per 16-lane half. Lane covers 8 floats of its
// row. Width-16 butterfly (4 steps) reduces both rows at once.
// ---------------------------------------------------------------------------
__global__ void __launch_bounds__(256, 8) sweep_kernel(
    const float* __restrict__ x,
    const float4* __restrict__ mem4,
    float4* __restrict__ out_mem4,
    float* __restrict__ logits,
    unsigned n_data) {
    __shared__ float4 xs[16 * 32];
    int tid = threadIdx.x;
    for (int i = tid; i < 16 * 32; i += blockDim.x)
        xs[i] = ((const float4*)x)[i];
    __syncthreads();

    unsigned lane = tid & 31u;
    unsigned half = lane >> 4;                    // which row of the pair
    unsigned hl = lane & 15u;                     // lane within half
    unsigned hmask = 0xFFFFu << (half * 16u);     // member mask of this half
    unsigned warp = ((unsigned)blockIdx.x * blockDim.x + tid) >> 5;
    unsigned nwarps = ((unsigned)gridDim.x * blockDim.x) >> 5;

    // per-thread xs base pointers (hoisted: b varies, hl fixed)
    const float4* xs0 = xs + hl;
    const float4* xs1 = xs + hl + 16u;

    for (unsigned rb = warp * 2u; rb < n_data; rb += nwarps * 2u) {
        unsigned r = rb + half;
        bool valid = r < n_data;
        unsigned rs = valid ? r : (n_data - 1u);

        // full 512B row per half: 2 float4 per lane (warp = 1KB contiguous)
        float4 m0 = __ldcs(mem4 + rs * 32u + hl);
        float4 m1 = __ldcs(mem4 + rs * 32u + hl + 16u);
        uint2 meta = g_meta[rs];
        unsigned c = valid ? (meta.x > CAP ? CAP : meta.x) : 0u;
        unsigned upd = valid ? meta.y : 0u;

        unsigned co = __shfl_xor_sync(0xffffffffu, c, 16);
        unsigned cmax = c > co ? c : co;          // warp-uniform

        const uint4* lst4 = (const uint4*)(g_list + (size_t)rs * CAP);
        for (unsigned base = 0; base < cmax; base += 4u) {
            uint4 L = lst4[base >> 2];            // 4 entries per LDG.128
            #pragma unroll
            for (int j = 0; j < 4; j++) {
                unsigned e = base + (unsigned)j;
                if (e >= cmax) break;             // warp-uniform exit
                bool act = e < c;
                unsigned ent = (j == 0) ? L.x : (j == 1) ? L.y
                             : (j == 2) ? L.z : L.w;
                unsigned b = (ent >> 24) & 15u;   // mask: garbage-safe
                unsigned i = ent & 0xFFFFFFu;
                float4 xv0 = xs0[b * 32u];
                float4 xv1 = xs1[b * 32u];
                float s = m0.x * xv0.x + m0.y * xv0.y + m0.z * xv0.z +
                          m0.w * xv0.w + m1.x * xv1.x + m1.y * xv1.y +
                          m1.z * xv1.z + m1.w * xv1.w;
                #pragma unroll
                for (int off = 8; off; off >>= 1)  // uniform: full mask OK
                    s += __shfl_xor_sync(0xffffffffu, s, off);
                if (act && hl == 0) logits[i] = s * T_INV;
            }
        }

        if (valid) {
            if (upd == 0) {
                float4* dst = out_mem4 + r * 32u;
                __stcs(dst + hl, m0);
                __stcs(dst + hl + 16u, m1);
            } else {
                // cold path, divergent within warp: per-half mask shuffles
                unsigned b = upd - 1u;
                float4 xv0 = xs0[b * 32u];
                float4 xv1 = xs1[b * 32u];
                float4 v0, v1;
                v0.x = 0.5f * (m0.x + xv0.x); v0.y = 0.5f * (m0.y + xv0.y);
                v0.z = 0.5f * (m0.z + xv0.z); v0.w = 0.5f * (m0.w + xv0.w);
                v1.x = 0.5f * (m1.x + xv1.x); v1.y = 0.5f * (m1.y + xv1.y);
                v1.z = 0.5f * (m1.z + xv1.z); v1.w = 0.5f * (m1.w + xv1.w);
                float s = v0.x * v0.x + v0.y * v0.y + v0.z * v0.z +
                          v0.w * v0.w + v1.x * v1.x + v1.y * v1.y +
                          v1.z * v1.z + v1.w * v1.w;
                #pragma unroll
                for (int off = 8; off; off >>= 1)
                    s += __shfl_xor_sync(hmask, s, off);
                float inv = 1.0f / fmaxf(sqrtf(s), 1e-12f);
                v0.x *= inv; v0.y *= inv; v0.z *= inv; v0.w *= inv;
                v1.x *= inv; v1.y *= inv; v1.z *= inv; v1.w *= inv;
                float4* dst = out_mem4 + r * 32u;
                __stcs(dst + hl, v0);
                __stcs(dst + hl + 16u, v1);
            }
            if (hl == 0) g_meta[r] = make_uint2(0u, 0u);  // self-clean
        }
    }
}

// ---------------------------------------------------------------------------
// Fallback path (shape out of range): R2-proven kernels.
// ---------------------------------------------------------------------------
__global__ void copy_mem_kernel(const float4* __restrict__ src,
                                float4* __restrict__ dst, long long n4) {
    long long i = (long long)blockIdx.x * blockDim.x + threadIdx.x;
    long long stride = (long long)gridDim.x * blockDim.x;
    for (; i < n4; i += stride) dst[i] = src[i];
}

__global__ void logits_kernel(const float* __restrict__ x,
                              const void* __restrict__ y,
                              const void* __restrict__ idx,
                              const float* __restrict__ memory,
                              float* __restrict__ logits,
                              int bsz, unsigned Kp1, long long n_data) {
    __shared__ float4 xs[16 * 32];
    __shared__ int s_is64;
    int tid = threadIdx.x;
    if (tid == 0) s_is64 = sniff_is64(idx);
    int nx4 = bsz * 32;
    for (int i = tid; i < nx4; i += blockDim.x) xs[i] = ((const float4*)x)[i];
    __syncthreads();
    int is64 = s_is64;

    int lane = tid & 31;
    unsigned warp = (blockIdx.x * blockDim.x + tid) >> 5;
    unsigned nwarps = (gridDim.x * blockDim.x) >> 5;
    unsigned total = (unsigned)bsz * Kp1;

    for (unsigned i = warp; i < total; i += nwarps) {
        unsigned b = i / Kp1;
        unsigned k = i - b * Kp1;
        long long row = (k == 0) ? load_index(y, b, is64)
                                 : load_index(idx, i, is64);
        row = row < 0 ? 0 : (row >= n_data ? n_data - 1 : row);
        float4 mm = __ldg((const float4*)(memory + row * 128) + lane);
        float4 xv = xs[b * 32 + lane];
        float s = mm.x * xv.x + mm.y * xv.y + mm.z * xv.z + mm.w * xv.w;
        #pragma unroll
        for (int off = 16; off; off >>= 1)
            s += __shfl_xor_sync(0xffffffffu, s, off);
        if (lane == 0) logits[i] = s * T_INV;
    }
}

__global__ void update_kernel(const float* __restrict__ x,
                              const void* __restrict__ y,
                              const void* __restrict__ idx,
                              const float* __restrict__ memory,
                              float* __restrict__ out_mem,
                              float* __restrict__ out_labels,
                              int label_elems, long long n_data) {
    int b = blockIdx.x;
    int t = threadIdx.x;
    __shared__ int s_is64;
    if (t == 0) s_is64 = sniff_is64(idx);
    __syncthreads();
    long long row = load_index(y, (unsigned)b, s_is64);
    row = row < 0 ? 0 : (row >= n_data ? n_data - 1 : row);

    float v = memory[row * 128 + t] * 0.5f + x[b * 128 + t] * 0.5f;
    float s = v * v;
    #pragma unroll
    for (int off = 16; off; off >>= 1)
        s += __shfl_xor_sync(0xffffffffu, s, off);
    __shared__ float ws[4];
    if ((t & 31) == 0) ws[t >> 5] = s;
    __syncthreads();
    float tot = ws[0] + ws[1] + ws[2] + ws[3];
    float denom = fmaxf(sqrtf(tot), 1e-12f);
    out_mem[row * 128 + t] = v / denom;
    if (b == 0 && t < label_elems) out_labels[t] = 0.0f;
}

// ---------------------------------------------------------------------------
extern "C" void kernel_launch(void* const* d_in, const int* in_sizes, int n_in,
                              void* d_out, int out_size) {
    const float* x      = (const float*)d_in[0];   // [bsz, 128]
    const void*  y      = d_in[1];                 // [bsz]
    const void*  idx    = d_in[2];                 // [bsz, K+1]
    const float* memory = (const float*)d_in[3];   // [n_data, 128]

    int bsz = in_sizes[1];
    unsigned Kp1 = (unsigned)(in_sizes[2] / bsz);
    long long mem_elems = (long long)in_sizes[3];
    long long n_data = mem_elems / 128;
    long long logits_elems = (long long)bsz * Kp1;

    float* out = (float*)d_out;
    long long mem_off = (long long)out_size - mem_elems;
    if (mem_off < logits_elems) mem_off = logits_elems;
    float* out_mem = out + mem_off;
    float* out_labels = out + logits_elems;
    int label_elems = (int)(mem_off - logits_elems);

    if (n_data <= MAX_ROWS && bsz <= 16 && logits_elems < (1 << 24)) {
        unsigned total = (unsigned)logits_elems;
        build_kernel<<<(total + 255) / 256, 256>>>(x, y, idx, memory, out,
                                                   out_labels, label_elems,
                                                   bsz, Kp1, n_data);
        sweep_kernel<<<2048, 256>>>(x, (const float4*)memory,
                                    (float4*)out_mem, out,
                                    (unsigned)n_data);
    } else {
        copy_mem_kernel<<<2048, 256>>>((const float4*)memory,
                                       (float4*)out_mem, mem_elems / 4);
        logits_kernel<<<1184, 256>>>(x, y, idx, memory, out,
                                     bsz, Kp1, n_data);
        update_kernel<<<bsz, 128>>>(x, y, idx, memory, out_mem, out_labels,
                                    label_elems, n_data);
    }
}